// round 14
// baseline (speedup 1.0000x reference)
#include <cuda_runtime.h>
#include <cuda_bf16.h>
#include <cstdint>

#define Kdim 256
#define Ndim 65536
#define TT   64                  // GEMM time-tile width
#define NT   (Ndim / TT)         // 1024

// ---------------- scratch (static device globals; no allocation) -------------
__device__ __nv_bfloat16 g_S[(size_t)Kdim * Ndim];   // [tile64][k][64] bf16
__device__ float  g_psum[Kdim * 4];
__device__ double g_ll;
__device__ int    g_done;

__device__ __forceinline__ void cpa16(unsigned dst, const void* src) {
    asm volatile("cp.async.cg.shared.global [%0], [%1], 16;" :: "r"(dst), "l"(src));
}

// ---------------- scan: truncated exponential-kernel recursion ---------------
// H(i) = decay*(H(i-1)+obs[k][i-1]) == fma(decay, H, decay*obs) -> 4cyc chain.
// decay <= e^-1 -> 32-step warmup error ~1e-14 << bf16 eps.
// cp.async staging; bf16 output written IN-PLACE over the consumed obs row
// (logical segs 0..7 written, neighbor warmup reads only segs 8..15) ->
// 64.1KB smem, low regs -> 3 CTAs/SM.
__global__ __launch_bounds__(256, 3) void k_scan(const float* __restrict__ obs,
                                                 const float* __restrict__ Beta) {
    extern __shared__ __align__(16) char sm[];
    const unsigned su = (unsigned)__cvta_generic_to_shared(sm);
    float* psr = (float*)(sm + 65536);               // 8 floats

    const int tid = threadIdx.x;
    const int k   = blockIdx.x >> 2;
    const int qtr = blockIdx.x & 3;
    const int x   = tid & 15;                        // row swizzle key
    if (blockIdx.x == 0 && tid == 0) { g_ll = 0.0; g_done = 0; }
    const float4* orow4 = (const float4*)(obs + (size_t)k * Ndim) + qtr * 4096;

    // ---- stage 64KB of obs (quarter row) via cp.async, seg-XOR swizzled rows
    #pragma unroll
    for (int i = 0; i < 16; ++i) {
        int idx = i * 256 + tid;             // float4 id, 0..4095
        int c = idx >> 4, s = idx & 15;
        cpa16(su + c * 256 + ((s ^ (c & 15)) << 4), orow4 + idx);
    }
    asm volatile("cp.async.commit_group;");
    asm volatile("cp.async.wait_group 0;" ::: "memory");
    __syncthreads();

    const float decay = __expf(-Beta[k]);

    // ---- warmup over obs[n0-32 .. n0-1] (neighbor row, logical segs 8..15)
    float h = 0.f, prev = 0.f;
    if (tid > 0) {
        const char* wrow = sm + (tid - 1) * 256;
        const int wx = (tid - 1) & 15;
        #pragma unroll
        for (int j = 0; j < 8; ++j) {
            float4 f = *(const float4*)(wrow + (((8 + j) ^ wx) << 4));
            h = __fmaf_rn(decay, h, f.x * decay);
            h = __fmaf_rn(decay, h, f.y * decay);
            h = __fmaf_rn(decay, h, f.z * decay);
            if (j < 7) h = __fmaf_rn(decay, h, f.w * decay); else prev = f.w;
        }
    } else if (qtr > 0) {
        const float4* g = (const float4*)(obs + (size_t)k * Ndim + qtr * 16384 - 32);
        #pragma unroll
        for (int j = 0; j < 8; ++j) {
            float4 f = __ldg(g + j);
            h = __fmaf_rn(decay, h, f.x * decay);
            h = __fmaf_rn(decay, h, f.y * decay);
            h = __fmaf_rn(decay, h, f.z * decay);
            if (j < 7) h = __fmaf_rn(decay, h, f.w * decay); else prev = f.w;
        }
    }
    // qtr==0 && tid==0: h=0, prev=0 -> H(0)=0 exactly as reference requires.

    // ---- recurrence over this thread's 64-step chunk; in-place packed output
    float sum = 0.f;
    char* row = sm + tid * 256;
    #pragma unroll
    for (int q = 0; q < 8; ++q) {
        float4 a = *(const float4*)(row + (((2 * q)     ^ x) << 4));
        float4 b = *(const float4*)(row + (((2 * q + 1) ^ x) << 4));
        float v[8] = {a.x, a.y, a.z, a.w, b.x, b.y, b.z, b.w};
        __nv_bfloat162 p[4];
        #pragma unroll
        for (int r = 0; r < 8; r += 2) {
            h = __fmaf_rn(decay, h, prev * decay);  float h0 = h;
            h = __fmaf_rn(decay, h, v[r] * decay);  float h1 = h;
            prev = v[r + 1];
            p[r >> 1] = __floats2bfloat162_rn(h0, h1);
            sum += v[r] + v[r + 1];
        }
        *(uint4*)(row + ((q ^ x) << 4)) = *(uint4*)p;   // logical seg q (< 2q+2)
    }

    // ---- block-reduce quarter-row sum -> one psum per block
    #pragma unroll
    for (int o = 16; o > 0; o >>= 1)
        sum += __shfl_down_sync(0xffffffffu, sum, o);
    if ((tid & 31) == 0) psr[tid >> 5] = sum;
    __syncthreads();                         // all rows packed & reads done
    if (tid == 0) {
        float s = 0.f;
        #pragma unroll
        for (int i = 0; i < 8; ++i) s += psr[i];
        g_psum[k * 4 + qtr] = s;
    }

    // ---- cooperative coalesced store into [tile64][k][64] blocks
    uint4* g4 = (uint4*)g_S;
    #pragma unroll
    for (int j = 0; j < 8; ++j) {
        int idx = j * 256 + tid;             // 0..2047
        int gc = idx >> 3, qq = idx & 7;
        uint4 v = *(const uint4*)(sm + gc * 256 + ((qq ^ (gc & 15)) << 4));
        int tile = qtr * 256 + gc;
        g4[((size_t)tile * Kdim + k) * 8 + qq] = v;
    }
}

// ---------------- lams0 broadcast fill (pure store stream) --------------------
// lams0[j][:] = Mu0[j] is tile-independent -> write it ONCE here at stream
// rate with evict-first stores (doesn't pollute L2 where S lives), removing
// 64MB (1/3) of the gemm's DRAM traffic. Rows are at out+1 (odd float offset):
// head 3 + tail 1 scalars, 16B-aligned float4 stores for the middle.
__global__ __launch_bounds__(256) void k_fill(float* __restrict__ out) {
    const int row = blockIdx.x >> 2, q = blockIdx.x & 3;
    const float4 ps = *(const float4*)(g_psum + row * 4);
    const float mu = ((ps.x + ps.y) + (ps.z + ps.w)) * (1.0f / Ndim) * 0.1f + 0.01f;
    float* base = out + 1 + (size_t)row * Ndim + q * 16384;
    const int t = threadIdx.x;
    if (t == 0) { base[0] = mu; base[1] = mu; base[2] = mu; base[16383] = mu; }
    const float4 v = make_float4(mu, mu, mu, mu);
    float4* b4 = (float4*)(base + 3);        // 16B aligned
    #pragma unroll
    for (int i = 0; i < 16; ++i) {
        int idx = i * 256 + t;
        if (idx < 4095) __stcs(b4 + idx, v);
    }
}

// ---------------- mma / ldmatrix helpers -------------------------------------
__device__ __forceinline__ void mma16816(float* c, const unsigned* a, unsigned b0, unsigned b1) {
    asm volatile(
        "mma.sync.aligned.m16n8k16.row.col.f32.bf16.bf16.f32 "
        "{%0,%1,%2,%3}, {%4,%5,%6,%7}, {%8,%9}, {%0,%1,%2,%3};\n"
        : "+f"(c[0]), "+f"(c[1]), "+f"(c[2]), "+f"(c[3])
        : "r"(a[0]), "r"(a[1]), "r"(a[2]), "r"(a[3]), "r"(b0), "r"(b1));
}
__device__ __forceinline__ void ldmx4(unsigned& r0, unsigned& r1, unsigned& r2, unsigned& r3,
                                      unsigned addr) {
    asm volatile("ldmatrix.sync.aligned.m8n8.x4.shared.b16 {%0,%1,%2,%3}, [%4];"
                 : "=r"(r0), "=r"(r1), "=r"(r2), "=r"(r3) : "r"(addr));
}
__device__ __forceinline__ void ldmx4t(unsigned& r0, unsigned& r1, unsigned& r2, unsigned& r3,
                                       unsigned addr) {
    asm volatile("ldmatrix.sync.aligned.m8n8.x4.trans.shared.b16 {%0,%1,%2,%3}, [%4];"
                 : "=r"(r0), "=r"(r1), "=r"(r2), "=r"(r3) : "r"(addr));
}

// smem byte offsets for k_gemm (per 512-thread CTA; 2 CTAs/SM)
#define SOFF_A   0               // 128 rows x 512B (this CTA's Alpha*Beta half)
#define SOFF_S   65536           // S tile: 256 k-rows x 128B (single buffer)
#define SOFF_BB  98304           // 16KB f32 bounce [64 j][64 t]
#define SOFF_MU  114688          // 128 floats
#define SOFF_RED 115200          // 16 doubles
#define SMEM_TOT 115328

// ---------------- fused GEMM (lam1 = softplus((Alpha*Beta) @ H)) + epilogue --
// 512 threads x 2 CTAs/SM, split along j (each CTA owns 128 rows). Single S
// buffer: next tile's cp.async issued right after the post-MMA sync, hidden
// behind the epilogue. lams0 is handled by k_fill; epilogue stores lams1 only.
__global__ __launch_bounds__(512, 2) void k_gemm(
    const float* __restrict__ obs,
    const float* __restrict__ Alpha,
    const float* __restrict__ Beta,
    float* __restrict__ out)
{
    extern __shared__ __align__(16) char smem[];
    const unsigned su = (unsigned)__cvta_generic_to_shared(smem);
    float*  Mu0s = (float*)(smem + SOFF_MU);
    double* red  = (double*)(smem + SOFF_RED);

    const int tid = threadIdx.x, wid = tid >> 5, lane = tid & 31;
    const int jh = blockIdx.x & 1;          // which 128-row j half
    const int wj = wid & 3;                 // 4 warps x 32 j rows
    const int wt = wid >> 2;                // 4 warps x 16 t cols
    const int jsw = lane & 7, subk = lane >> 4;
    const int lg = lane >> 2, lm = lane & 3;
    const int G2 = gridDim.x >> 1;
    const int t0 = blockIdx.x >> 1;

    // ---- prologue: prefetch tile t0 -> S buffer
    {
        const char* src = (const char*)g_S + (size_t)t0 * 32768;
        #pragma unroll
        for (int i = 0; i < 4; ++i) {
            int idx = tid + i * 512;        // 0..2047
            int k = idx >> 3, s = idx & 7;
            cpa16(su + SOFF_S + k * 128 + ((s ^ (k & 7)) << 4), src + idx * 16);
        }
        asm volatile("cp.async.commit_group;");
    }

    // ---- stage this half's Alpha*Beta -> swizzled bf16 smem (rows 512B)
    {
        const float4* A4 = (const float4*)Alpha;
        const float4* B4 = (const float4*)Beta;
        #pragma unroll
        for (int ii = 0; ii < 8; ++ii) {
            int idx = tid + ii * 512;       // 16B chunks, 0..4095
            int jl = idx >> 5, s = idx & 31;
            int jg = jh * 128 + jl;
            float4 v0 = A4[jg * 64 + s * 2];
            float4 v1 = A4[jg * 64 + s * 2 + 1];
            float4 b0 = __ldg(B4 + s * 2);
            float4 b1 = __ldg(B4 + s * 2 + 1);
            __nv_bfloat162 pk[4];
            pk[0] = __floats2bfloat162_rn(v0.x * b0.x, v0.y * b0.y);
            pk[1] = __floats2bfloat162_rn(v0.z * b0.z, v0.w * b0.w);
            pk[2] = __floats2bfloat162_rn(v1.x * b1.x, v1.y * b1.y);
            pk[3] = __floats2bfloat162_rn(v1.z * b1.z, v1.w * b1.w);
            int phys = (s & 24) | ((s & 7) ^ (jl & 7));
            *(uint4*)(smem + SOFF_A + jl * 512 + phys * 16) = *(uint4*)pk;
        }
        if (tid < 128) {
            float4 ps = *(const float4*)(g_psum + (jh * 128 + tid) * 4);
            Mu0s[tid] = ((ps.x + ps.y) + (ps.z + ps.w)) * (1.0f / Ndim) * 0.1f + 0.01f;
        }
    }

    // ---- precomputed lane addresses
    unsigned ja[2];
    #pragma unroll
    for (int mf = 0; mf < 2; ++mf) {
        int jrow = wj * 32 + mf * 16 + (lane & 8) + jsw;   // local 0..127
        ja[mf] = su + SOFF_A + jrow * 512;
    }
    const unsigned boct0 = (unsigned)(lane * 128 + (((wt * 2 + 0) ^ jsw) << 4));
    const unsigned boct1 = (unsigned)(lane * 128 + (((wt * 2 + 1) ^ jsw) << 4));

    float*  lams1 = out + 1 + (size_t)Kdim * Ndim;
    float*  Bf  = (float*)(smem + SOFF_BB);
    float2* Bf2 = (float2*)Bf;

    double lsum = 0.0;

    for (int tile = t0; tile < NT; tile += G2) {
        asm volatile("cp.async.wait_group 0;" ::: "memory");
        __syncthreads();                    // S ready; BB free (prev iter done)

        // ---- MMA
        float acc[2][2][4];
        #pragma unroll
        for (int a = 0; a < 2; ++a)
            #pragma unroll
            for (int b = 0; b < 2; ++b)
                #pragma unroll
                for (int d = 0; d < 4; ++d) acc[a][b][d] = 0.f;

        #pragma unroll
        for (int ks2 = 0; ks2 < 8; ++ks2) {
            unsigned c0, c1, c2, c3, d0, d1, d2, d3;
            ldmx4t(c0, c1, c2, c3, su + SOFF_S + boct0 + ks2 * 4096);
            ldmx4t(d0, d1, d2, d3, su + SOFF_S + boct1 + ks2 * 4096);
            #pragma unroll
            for (int hh = 0; hh < 2; ++hh) {
                const int sA = (ks2 * 2 + hh) * 2 + subk;
                const unsigned aoff = (unsigned)(((sA & 24) | ((sA & 7) ^ jsw)) << 4);
                const unsigned cx = hh ? c2 : c0, cy = hh ? c3 : c1;
                const unsigned dx = hh ? d2 : d0, dy = hh ? d3 : d1;
                #pragma unroll
                for (int mf = 0; mf < 2; ++mf) {
                    unsigned a[4];
                    ldmx4(a[0], a[1], a[2], a[3], ja[mf] + aoff);
                    mma16816(acc[mf][0], a, cx, cy);
                    mma16816(acc[mf][1], a, dx, dy);
                }
            }
        }
        __syncthreads();                    // all MMA reads of S done

        // ---- issue next tile's load into S (hidden behind epilogue)
        {
            int nxt = tile + G2;
            if (nxt < NT) {
                const char* src = (const char*)g_S + (size_t)nxt * 32768;
                #pragma unroll
                for (int i = 0; i < 4; ++i) {
                    int idx = tid + i * 512;
                    int k = idx >> 3, s = idx & 7;
                    cpa16(su + SOFF_S + k * 128 + ((s ^ (k & 7)) << 4), src + idx * 16);
                }
            }
            asm volatile("cp.async.commit_group;");
        }

        // ---- epilogue: 2 j-slices of 64 rows through the bounce
        const int n0 = tile * TT;
        #pragma unroll
        for (int s = 0; s < 2; ++s) {
            if ((wj >> 1) == s) {
                #pragma unroll
                for (int mf = 0; mf < 2; ++mf)
                    #pragma unroll
                    for (int half = 0; half < 2; ++half) {
                        const int jl = (wj & 1) * 32 + mf * 16 + lg + half * 8;
                        #pragma unroll
                        for (int nf = 0; nf < 2; ++nf) {
                            const int gsw = (wt * 2 + nf) ^ (jl & 7);
                            Bf2[jl * 32 + gsw * 4 + lm] =
                                make_float2(acc[mf][nf][half * 2], acc[mf][nf][half * 2 + 1]);
                        }
                    }
            }
            __syncthreads();   // bounce slice visible

            float fsum = 0.f;
            #pragma unroll
            for (int rr = 0; rr < 4; ++rr) {
                const int jl = wid * 4 + rr;              // 0..63
                const int jg = jh * 128 + s * 64 + jl;
                const float mu = Mu0s[s * 64 + jl];
                const size_t rowbase = (size_t)jg * Ndim + n0;
                #pragma unroll
                for (int pass = 0; pass < 2; ++pass) {
                    const int tof = pass * 32 + lane;
                    float z = Bf[jl * 64 + (((tof >> 3) ^ (jl & 7)) << 3) + (tof & 7)];
                    float lam = z + __logf(1.f + __expf(-z));   // softplus, z>=0
                    if (n0 + tof == 0) lam = 0.f;   // reference: lams1[:,0] = 0
                    const size_t base = rowbase + tof;
                    lams1[base] = lam;
                    float o = __ldg(obs + base);
                    fsum += o * __logf(mu + lam + 1e-5f) - mu - lam;
                }
            }
            lsum += (double)fsum;
            if (s == 0) __syncthreads();   // slice-0 reads done before slice-1 writes
            // s==1: next-iter top sync protects BB reuse
        }
    }
    asm volatile("cp.async.wait_group 0;" ::: "memory");   // drain tail

    // ---- loglik reduction + folded final write
    #pragma unroll
    for (int o = 16; o > 0; o >>= 1)
        lsum += __shfl_down_sync(0xffffffffu, lsum, o);
    if (lane == 0) red[wid] = lsum;
    __syncthreads();
    if (tid == 0) {
        double s = 0.0;
        #pragma unroll
        for (int i = 0; i < 16; ++i) s += red[i];
        atomicAdd(&g_ll, s);
        __threadfence();
        int done = atomicAdd(&g_done, 1);
        if (done == gridDim.x - 1) {
            out[0] = (float)atomicAdd(&g_ll, 0.0);   // coherent read of final sum
            g_done = 0;                              // reset for next graph replay
        }
    }
}

// ---------------- launch ------------------------------------------------------
extern "C" void kernel_launch(void* const* d_in, const int* in_sizes, int n_in,
                              void* d_out, int out_size) {
    const float* obs   = (const float*)d_in[0];
    const float* Beta  = (const float*)d_in[1];
    const float* Alpha = (const float*)d_in[2];
    float* out = (float*)d_out;

    const int scan_smem = 65536 + 64;   // 64KB obs block + psum scratch
    cudaFuncSetAttribute(k_scan, cudaFuncAttributeMaxDynamicSharedMemorySize, scan_smem);
    k_scan<<<Kdim * 4, 256, scan_smem>>>(obs, Beta);

    k_fill<<<Kdim * 4, 256>>>(out);

    cudaFuncSetAttribute(k_gemm, cudaFuncAttributeMaxDynamicSharedMemorySize, SMEM_TOT);
    int nsm = 148;
    cudaDeviceGetAttribute(&nsm, cudaDevAttrMultiProcessorCount, 0);
    k_gemm<<<2 * nsm, 512, SMEM_TOT>>>(obs, Alpha, Beta, out);
}